// round 6
// baseline (speedup 1.0000x reference)
#include <cuda_runtime.h>
#include <cuda_bf16.h>
#include <cstdint>

// Problem dims
#define NSEQ 4096
#define DIM  1024

// GEMM tiling
#define BM 128
#define BN 128
#define BK 32
#define STG 3
#define ROW_PITCH 144                    // 36 floats: conflict-free for ldmatrix
#define B_OFF (BM * ROW_PITCH)           // 18432
#define STAGE_BYTES (2 * BM * ROW_PITCH) // 36864
#define DYN_SMEM_BYTES (STG * STAGE_BYTES)

// ---------------- scratch (static device allocations; no cudaMalloc) ----------------
__device__ float g_xt[NSEQ * DIM];
__device__ float g_wt[3 * DIM * DIM];          // stacked [3072, 1024]
__device__ float g_qkv[NSEQ * 3 * DIM];        // packed [4096, 3072]: Q|K|V
__device__ float g_vt[DIM * NSEQ];             // V^T [1024, 4096]
__device__ float g_S[(size_t)NSEQ * NSEQ];
__device__ float g_P[(size_t)NSEQ * NSEQ];

// ---------------- helpers ----------------
__device__ __forceinline__ float to_tf32(float x) {
    uint32_t u;
    asm volatile("cvt.rna.tf32.f32 %0, %1;" : "=r"(u) : "f"(x));
    return __uint_as_float(u);
}

__device__ __forceinline__ uint32_t smem_u32(const void* p) {
    return (uint32_t)__cvta_generic_to_shared(p);
}

__device__ __forceinline__ uint64_t gmem_u64(const void* p) {
    uint64_t g;
    asm volatile("cvta.to.global.u64 %0, %1;" : "=l"(g) : "l"(p));
    return g;
}

__device__ __forceinline__ void ldsm_x4(uint32_t& r0, uint32_t& r1, uint32_t& r2, uint32_t& r3,
                                        uint32_t addr) {
    asm volatile("ldmatrix.sync.aligned.m8n8.x4.shared.b16 {%0,%1,%2,%3}, [%4];\n"
                 : "=r"(r0), "=r"(r1), "=r"(r2), "=r"(r3)
                 : "r"(addr));
}

__device__ __forceinline__ void mma_tf32(float c[4], uint32_t a0, uint32_t a1, uint32_t a2,
                                         uint32_t a3, uint32_t b0, uint32_t b1) {
    asm volatile(
        "mma.sync.aligned.m16n8k8.row.col.f32.tf32.tf32.f32 "
        "{%0,%1,%2,%3}, {%4,%5,%6,%7}, {%8,%9}, {%0,%1,%2,%3};\n"
        : "+f"(c[0]), "+f"(c[1]), "+f"(c[2]), "+f"(c[3])
        : "r"(a0), "r"(a1), "r"(a2), "r"(a3), "r"(b0), "r"(b1));
}

#define CP_ASYNC16(dst, src) \
    asm volatile("cp.async.cg.shared.global [%0], [%1], 16;" :: "r"(dst), "l"(src))
#define CP_COMMIT() asm volatile("cp.async.commit_group;" ::: "memory")

// ---------------- convert inputs: fp32 -> tf32-rounded fp32 ----------------
__global__ void convert_kernel(const float* __restrict__ x, const float* __restrict__ wq,
                               const float* __restrict__ wk, const float* __restrict__ wv) {
    const int stride = gridDim.x * blockDim.x;
    const int tid = blockIdx.x * blockDim.x + threadIdx.x;
    const int nx4 = (NSEQ * DIM) / 4;
    for (int i = tid; i < nx4; i += stride) {
        float4 f = ((const float4*)x)[i];
        ((float4*)g_xt)[i] = make_float4(to_tf32(f.x), to_tf32(f.y), to_tf32(f.z), to_tf32(f.w));
    }
    const int nw4 = (DIM * DIM) / 4;
    for (int i = tid; i < nw4; i += stride) {
        float4 a = ((const float4*)wq)[i];
        float4 b = ((const float4*)wk)[i];
        float4 c = ((const float4*)wv)[i];
        ((float4*)g_wt)[i]           = make_float4(to_tf32(a.x), to_tf32(a.y), to_tf32(a.z), to_tf32(a.w));
        ((float4*)g_wt)[nw4 + i]     = make_float4(to_tf32(b.x), to_tf32(b.y), to_tf32(b.z), to_tf32(b.w));
        ((float4*)g_wt)[2 * nw4 + i] = make_float4(to_tf32(c.x), to_tf32(c.y), to_tf32(c.z), to_tf32(c.w));
    }
}

// ======== tf32 mma.sync GEMM with 3-stage cp.async pipeline =========================
// C[M,N] = A[M,K] * B[N,K]^T ; A rows stride ldA, B rows stride ldB, C rows stride ldC.
// 128x128x32 CTA tile, 8 warps (2x4), warp tile 64x32.
__global__ __launch_bounds__(256, 1)
void gemm_tt(const float* __restrict__ A, int ldA, const float* __restrict__ B, int ldB,
             float* __restrict__ C, int ldC, int M, int N, int K, int round_out) {
    extern __shared__ char dynsm[];
    const uint32_t sm_base = smem_u32(dynsm);

    const int tid  = threadIdx.x;
    const int lane = tid & 31;
    const int warp = tid >> 5;
    const int wm = warp >> 2;   // 0..1 -> m offset wm*64
    const int wn = warp & 3;    // 0..3 -> n offset wn*32

    const int rm0 = blockIdx.y * BM;
    const int cn0 = blockIdx.x * BN;
    const int nchunks = K / BK;

    const uint64_t gA = gmem_u64(A);
    const uint64_t gB = gmem_u64(B);

    float c[4][4][4];
#pragma unroll
    for (int i = 0; i < 4; i++)
#pragma unroll
        for (int j = 0; j < 4; j++)
#pragma unroll
            for (int r = 0; r < 4; r++) c[i][j][r] = 0.f;

    // fill stage `stg` with K-chunk `ck`
    auto fill = [&](int ck, int stg) {
        const uint32_t s0 = sm_base + stg * STAGE_BYTES;
        const uint64_t baseA = gA + ((size_t)rm0 * ldA + ck * BK) * 4;
        const uint64_t baseB = gB + ((size_t)cn0 * ldB + ck * BK) * 4;
#pragma unroll
        for (int t = 0; t < 4; t++) {
            int idx = tid + t * 256;   // 0..1023
            int r = idx >> 3, q = idx & 7;
            CP_ASYNC16(s0 + r * ROW_PITCH + q * 16, baseA + ((size_t)r * ldA + q * 4) * 4);
        }
#pragma unroll
        for (int t = 0; t < 4; t++) {
            int idx = tid + t * 256;
            int r = idx >> 3, q = idx & 7;
            CP_ASYNC16(s0 + B_OFF + r * ROW_PITCH + q * 16, baseB + ((size_t)r * ldB + q * 4) * 4);
        }
    };

    // prologue: chunks 0,1 -> stages 0,1
    fill(0, 0); CP_COMMIT();
    fill(1, 1); CP_COMMIT();

    for (int i = 0; i < nchunks; i++) {
        const int s = i % STG;
        if (i + 2 < nchunks) {
            asm volatile("cp.async.wait_group 1;" ::: "memory");
        } else {
            asm volatile("cp.async.wait_group 0;" ::: "memory");
        }
        __syncthreads();

        // kick off the load for chunk i+2 (into the stage freed by chunk i-1)
        if (i + 2 < nchunks) {
            fill(i + 2, (i + 2) % STG);
            CP_COMMIT();
        }

        const uint32_t sA = sm_base + s * STAGE_BYTES;
        const uint32_t sB = sA + B_OFF;
#pragma unroll
        for (int kk = 0; kk < BK; kk += 8) {
            uint32_t a[4][4], b[4][2];
#pragma unroll
            for (int i2 = 0; i2 < 4; i2++) {
                uint32_t addr = sA + (wm * 64 + i2 * 16 + (lane & 15)) * ROW_PITCH +
                                (kk + ((lane >> 4) << 2)) * 4;
                ldsm_x4(a[i2][0], a[i2][1], a[i2][2], a[i2][3], addr);
            }
#pragma unroll
            for (int j0 = 0; j0 < 4; j0 += 2) {
                int pair = lane >> 3;
                uint32_t addr = sB + (wn * 32 + (j0 + (pair >> 1)) * 8 + (lane & 7)) * ROW_PITCH +
                                (kk + ((pair & 1) << 2)) * 4;
                uint32_t r0, r1, r2, r3;
                ldsm_x4(r0, r1, r2, r3, addr);
                b[j0][0] = r0; b[j0][1] = r1; b[j0 + 1][0] = r2; b[j0 + 1][1] = r3;
            }
#pragma unroll
            for (int i2 = 0; i2 < 4; i2++)
#pragma unroll
                for (int j = 0; j < 4; j++)
                    mma_tf32(c[i2][j], a[i2][0], a[i2][1], a[i2][2], a[i2][3], b[j][0], b[j][1]);
        }
    }

    // epilogue
    const int tr = lane >> 2;
    const int tc = (lane & 3) * 2;
#pragma unroll
    for (int i = 0; i < 4; i++) {
#pragma unroll
        for (int j = 0; j < 4; j++) {
            size_t row = (size_t)(rm0 + wm * 64 + i * 16 + tr);
            int col = cn0 + wn * 32 + j * 8 + tc;
            float v0 = c[i][j][0], v1 = c[i][j][1], v2 = c[i][j][2], v3 = c[i][j][3];
            if (round_out) { v0 = to_tf32(v0); v1 = to_tf32(v1); v2 = to_tf32(v2); v3 = to_tf32(v3); }
            *(float2*)&C[row * ldC + col]       = make_float2(v0, v1);
            *(float2*)&C[(row + 8) * ldC + col] = make_float2(v2, v3);
        }
    }
}

// ---------------- transpose: Vt[c][r] = QKV[r][2048 + c] ----------------
__global__ void transpose_v_kernel(const float* __restrict__ qkv, float* __restrict__ out) {
    __shared__ float tile[32][33];
    int cbase = blockIdx.x * 32;   // headdim index
    int rbase = blockIdx.y * 32;   // seq index
    int tx = threadIdx.x, ty = threadIdx.y;
#pragma unroll
    for (int j = 0; j < 32; j += 8)
        tile[ty + j][tx] = qkv[(size_t)(rbase + ty + j) * (3 * DIM) + 2 * DIM + cbase + tx];
    __syncthreads();
#pragma unroll
    for (int j = 0; j < 32; j += 8)
        out[(size_t)(cbase + ty + j) * NSEQ + rbase + tx] = tile[tx][ty + j];
}

// ---------------- row softmax: P = softmax(S * 1/32), output tf32-rounded ----------------
__global__ __launch_bounds__(256)
void softmax_kernel(const float* __restrict__ S, float* __restrict__ P) {
    const int row = blockIdx.x;
    const float scale = 0.03125f;   // 1/sqrt(1024)
    const float* s = S + (size_t)row * NSEQ;
    float* p = P + (size_t)row * NSEQ;
    const int tid = threadIdx.x;
    const int lane = tid & 31, warp = tid >> 5;
    __shared__ float sh[8];

    float v[16];
    float mx = -1e30f;
#pragma unroll
    for (int t = 0; t < 16; t++) {
        v[t] = s[tid + t * 256] * scale;
        mx = fmaxf(mx, v[t]);
    }
#pragma unroll
    for (int o = 16; o; o >>= 1) mx = fmaxf(mx, __shfl_xor_sync(0xffffffffu, mx, o));
    if (lane == 0) sh[warp] = mx;
    __syncthreads();
    if (tid == 0) {
        float t = sh[0];
#pragma unroll
        for (int i = 1; i < 8; i++) t = fmaxf(t, sh[i]);
        sh[0] = t;
    }
    __syncthreads();
    mx = sh[0];
    __syncthreads();

    float sum = 0.f;
#pragma unroll
    for (int t = 0; t < 16; t++) {
        v[t] = __expf(v[t] - mx);
        sum += v[t];
    }
#pragma unroll
    for (int o = 16; o; o >>= 1) sum += __shfl_xor_sync(0xffffffffu, sum, o);
    if (lane == 0) sh[warp] = sum;
    __syncthreads();
    if (tid == 0) {
        float t = 0.f;
#pragma unroll
        for (int i = 0; i < 8; i++) t += sh[i];
        sh[0] = t;
    }
    __syncthreads();
    const float inv = 1.0f / sh[0];
#pragma unroll
    for (int t = 0; t < 16; t++) p[tid + t * 256] = to_tf32(v[t] * inv);
}

// ---------------- launch ----------------
extern "C" void kernel_launch(void* const* d_in, const int* in_sizes, int n_in,
                              void* d_out, int out_size) {
    const float* x  = (const float*)d_in[0];
    const float* wq = (const float*)d_in[1];
    const float* wk = (const float*)d_in[2];
    const float* wv = (const float*)d_in[3];
    float* out = (float*)d_out;

    float *p_xt, *p_wt, *p_qkv, *p_vt, *p_S, *p_P;
    cudaGetSymbolAddress((void**)&p_xt, g_xt);
    cudaGetSymbolAddress((void**)&p_wt, g_wt);
    cudaGetSymbolAddress((void**)&p_qkv, g_qkv);
    cudaGetSymbolAddress((void**)&p_vt, g_vt);
    cudaGetSymbolAddress((void**)&p_S, g_S);
    cudaGetSymbolAddress((void**)&p_P, g_P);

    cudaFuncSetAttribute(gemm_tt, cudaFuncAttributeMaxDynamicSharedMemorySize, DYN_SMEM_BYTES);

    // 1) round inputs to tf32
    convert_kernel<<<2048, 256>>>(x, wq, wk, wv);

    // 2) QKV = x @ W^T, W stacked [3072,1024]; output packed [4096, 3072]
    gemm_tt<<<dim3(3 * DIM / BN, NSEQ / BM), 256, DYN_SMEM_BYTES>>>(
        p_xt, DIM, p_wt, DIM, p_qkv, 3 * DIM, NSEQ, 3 * DIM, DIM, 1);

    // 3) V^T for the P@V GEMM
    transpose_v_kernel<<<dim3(DIM / 32, NSEQ / 32), dim3(32, 8)>>>(p_qkv, p_vt);

    // 4) S = Q @ K^T  (M=N=4096, K=1024); Q,K are column slices of packed qkv
    gemm_tt<<<dim3(NSEQ / BN, NSEQ / BM), 256, DYN_SMEM_BYTES>>>(
        p_qkv, 3 * DIM, p_qkv + DIM, 3 * DIM, p_S, NSEQ, NSEQ, NSEQ, DIM, 0);

    // 5) P = softmax(S / 32), tf32-rounded
    softmax_kernel<<<NSEQ, 256>>>(p_S, p_P);

    // 6) out = P @ V = P @ (V^T)^T  (M=4096, N=1024, K=4096)
    gemm_tt<<<dim3(DIM / BN, NSEQ / BM), 256, DYN_SMEM_BYTES>>>(
        p_P, NSEQ, p_vt, NSEQ, out, DIM, NSEQ, DIM, NSEQ, 0);
}

// round 7
// speedup vs baseline: 1.1702x; 1.1702x over previous
#include <cuda_runtime.h>
#include <cuda_bf16.h>
#include <cstdint>

// Problem dims
#define NSEQ 4096
#define DIM  1024

// GEMM tiling
#define BM 128
#define BN 128
#define BK 32
#define STG 3
#define ROW_PITCH 144                    // 36 floats: conflict-free for ldmatrix
#define B_OFF (BM * ROW_PITCH)           // 18432
#define STAGE_BYTES (2 * BM * ROW_PITCH) // 36864
#define DYN_SMEM_BYTES (STG * STAGE_BYTES)   // 108 KB -> 2 CTAs/SM fit in 228 KB

// ---------------- scratch (static device allocations; no cudaMalloc) ----------------
__device__ float g_xt[NSEQ * DIM];
__device__ float g_wt[3 * DIM * DIM];          // stacked [3072, 1024]
__device__ float g_qkv[NSEQ * 3 * DIM];        // packed [4096, 3072]: Q|K|V
__device__ float g_vt[DIM * NSEQ];             // V^T [1024, 4096]
__device__ float g_S[(size_t)NSEQ * NSEQ];
__device__ float g_P[(size_t)NSEQ * NSEQ];

// ---------------- helpers ----------------
__device__ __forceinline__ float to_tf32(float x) {
    uint32_t u;
    asm volatile("cvt.rna.tf32.f32 %0, %1;" : "=r"(u) : "f"(x));
    return __uint_as_float(u);
}

__device__ __forceinline__ uint32_t smem_u32(const void* p) {
    return (uint32_t)__cvta_generic_to_shared(p);
}

__device__ __forceinline__ uint64_t gmem_u64(const void* p) {
    uint64_t g;
    asm volatile("cvta.to.global.u64 %0, %1;" : "=l"(g) : "l"(p));
    return g;
}

__device__ __forceinline__ void ldsm_x4(uint32_t& r0, uint32_t& r1, uint32_t& r2, uint32_t& r3,
                                        uint32_t addr) {
    asm volatile("ldmatrix.sync.aligned.m8n8.x4.shared.b16 {%0,%1,%2,%3}, [%4];\n"
                 : "=r"(r0), "=r"(r1), "=r"(r2), "=r"(r3)
                 : "r"(addr));
}

__device__ __forceinline__ void mma_tf32(float c[4], uint32_t a0, uint32_t a1, uint32_t a2,
                                         uint32_t a3, uint32_t b0, uint32_t b1) {
    asm volatile(
        "mma.sync.aligned.m16n8k8.row.col.f32.tf32.tf32.f32 "
        "{%0,%1,%2,%3}, {%4,%5,%6,%7}, {%8,%9}, {%0,%1,%2,%3};\n"
        : "+f"(c[0]), "+f"(c[1]), "+f"(c[2]), "+f"(c[3])
        : "r"(a0), "r"(a1), "r"(a2), "r"(a3), "r"(b0), "r"(b1));
}

#define CP_ASYNC16(dst, src) \
    asm volatile("cp.async.cg.shared.global [%0], [%1], 16;" :: "r"(dst), "l"(src))
#define CP_COMMIT() asm volatile("cp.async.commit_group;" ::: "memory")

// ---------------- convert inputs: fp32 -> tf32-rounded fp32 ----------------
__global__ void convert_kernel(const float* __restrict__ x, const float* __restrict__ wq,
                               const float* __restrict__ wk, const float* __restrict__ wv) {
    const int stride = gridDim.x * blockDim.x;
    const int tid = blockIdx.x * blockDim.x + threadIdx.x;
    const int nx4 = (NSEQ * DIM) / 4;
    for (int i = tid; i < nx4; i += stride) {
        float4 f = ((const float4*)x)[i];
        ((float4*)g_xt)[i] = make_float4(to_tf32(f.x), to_tf32(f.y), to_tf32(f.z), to_tf32(f.w));
    }
    const int nw4 = (DIM * DIM) / 4;
    for (int i = tid; i < nw4; i += stride) {
        float4 a = ((const float4*)wq)[i];
        float4 b = ((const float4*)wk)[i];
        float4 c = ((const float4*)wv)[i];
        ((float4*)g_wt)[i]           = make_float4(to_tf32(a.x), to_tf32(a.y), to_tf32(a.z), to_tf32(a.w));
        ((float4*)g_wt)[nw4 + i]     = make_float4(to_tf32(b.x), to_tf32(b.y), to_tf32(b.z), to_tf32(b.w));
        ((float4*)g_wt)[2 * nw4 + i] = make_float4(to_tf32(c.x), to_tf32(c.y), to_tf32(c.z), to_tf32(c.w));
    }
}

// ======== tf32 mma.sync GEMM, 3-stage cp.async pipeline, 2 CTAs/SM ==================
// C[M,N] = A[M,K] * B[N,K]^T ; row strides ldA/ldB/ldC.
// 128x128x32 CTA tile, 8 warps (2x4), warp tile 64x32.
__global__ __launch_bounds__(256, 2)
void gemm_tt(const float* __restrict__ A, int ldA, const float* __restrict__ B, int ldB,
             float* __restrict__ C, int ldC, int M, int N, int K, int round_out) {
    extern __shared__ char dynsm[];
    const uint32_t sm_base = smem_u32(dynsm);

    const int tid  = threadIdx.x;
    const int lane = tid & 31;
    const int warp = tid >> 5;
    const int wm = warp >> 2;   // 0..1 -> m offset wm*64
    const int wn = warp & 3;    // 0..3 -> n offset wn*32

    const int rm0 = blockIdx.y * BM;
    const int cn0 = blockIdx.x * BN;
    const int nchunks = K / BK;

    // per-thread load geometry: row r0 = tid>>3 (+32 per t), 16B col q
    const int r0 = tid >> 3;
    const int q  = tid & 7;
    // global base pointers, advanced by BK*4 bytes per chunk
    uint64_t pA = gmem_u64(A) + ((size_t)(rm0 + r0) * ldA + q * 4) * 4;
    uint64_t pB = gmem_u64(B) + ((size_t)(cn0 + r0) * ldB + q * 4) * 4;
    const uint64_t stA = (uint64_t)ldA * 32 * 4;   // +32 rows
    const uint64_t stB = (uint64_t)ldB * 32 * 4;
    const uint32_t sOffA = r0 * ROW_PITCH + q * 16;
    const uint32_t sOffB = B_OFF + sOffA;

    float c[4][4][4];
#pragma unroll
    for (int i = 0; i < 4; i++)
#pragma unroll
        for (int j = 0; j < 4; j++)
#pragma unroll
            for (int r = 0; r < 4; r++) c[i][j][r] = 0.f;

    // fill stage `stg` with the K-chunk currently addressed by pA/pB, then advance
    auto fill = [&](int stg) {
        const uint32_t s0 = sm_base + stg * STAGE_BYTES;
#pragma unroll
        for (int t = 0; t < 4; t++)
            CP_ASYNC16(s0 + sOffA + t * (32 * ROW_PITCH), pA + t * stA);
#pragma unroll
        for (int t = 0; t < 4; t++)
            CP_ASYNC16(s0 + sOffB + t * (32 * ROW_PITCH), pB + t * stB);
        pA += BK * 4;
        pB += BK * 4;
    };

    // prologue: chunks 0,1 -> stages 0,1
    fill(0); CP_COMMIT();
    fill(1); CP_COMMIT();

    for (int i = 0; i < nchunks; i++) {
        const int s = i % STG;
        if (i + 2 < nchunks) {
            asm volatile("cp.async.wait_group 1;" ::: "memory");
        } else {
            asm volatile("cp.async.wait_group 0;" ::: "memory");
        }
        __syncthreads();

        // kick off the load for chunk i+2 (into the stage freed by chunk i-1)
        if (i + 2 < nchunks) {
            fill((i + 2) % STG);
            CP_COMMIT();
        }

        const uint32_t sA = sm_base + s * STAGE_BYTES;
        const uint32_t sB = sA + B_OFF;
#pragma unroll
        for (int kk = 0; kk < BK; kk += 8) {
            uint32_t a[4][4], b[4][2];
#pragma unroll
            for (int i2 = 0; i2 < 4; i2++) {
                uint32_t addr = sA + (wm * 64 + i2 * 16 + (lane & 15)) * ROW_PITCH +
                                (kk + ((lane >> 4) << 2)) * 4;
                ldsm_x4(a[i2][0], a[i2][1], a[i2][2], a[i2][3], addr);
            }
#pragma unroll
            for (int j0 = 0; j0 < 4; j0 += 2) {
                int pair = lane >> 3;
                uint32_t addr = sB + (wn * 32 + (j0 + (pair >> 1)) * 8 + (lane & 7)) * ROW_PITCH +
                                (kk + ((pair & 1) << 2)) * 4;
                uint32_t r0_, r1_, r2_, r3_;
                ldsm_x4(r0_, r1_, r2_, r3_, addr);
                b[j0][0] = r0_; b[j0][1] = r1_; b[j0 + 1][0] = r2_; b[j0 + 1][1] = r3_;
            }
#pragma unroll
            for (int i2 = 0; i2 < 4; i2++)
#pragma unroll
                for (int j = 0; j < 4; j++)
                    mma_tf32(c[i2][j], a[i2][0], a[i2][1], a[i2][2], a[i2][3], b[j][0], b[j][1]);
        }
    }

    // epilogue
    const int tr = lane >> 2;
    const int tc = (lane & 3) * 2;
#pragma unroll
    for (int i = 0; i < 4; i++) {
#pragma unroll
        for (int j = 0; j < 4; j++) {
            size_t row = (size_t)(rm0 + wm * 64 + i * 16 + tr);
            int col = cn0 + wn * 32 + j * 8 + tc;
            float v0 = c[i][j][0], v1 = c[i][j][1], v2 = c[i][j][2], v3 = c[i][j][3];
            if (round_out) { v0 = to_tf32(v0); v1 = to_tf32(v1); v2 = to_tf32(v2); v3 = to_tf32(v3); }
            *(float2*)&C[row * ldC + col]       = make_float2(v0, v1);
            *(float2*)&C[(row + 8) * ldC + col] = make_float2(v2, v3);
        }
    }
}

// ---------------- transpose: Vt[c][r] = QKV[r][2048 + c] ----------------
__global__ void transpose_v_kernel(const float* __restrict__ qkv, float* __restrict__ out) {
    __shared__ float tile[32][33];
    int cbase = blockIdx.x * 32;   // headdim index
    int rbase = blockIdx.y * 32;   // seq index
    int tx = threadIdx.x, ty = threadIdx.y;
#pragma unroll
    for (int j = 0; j < 32; j += 8)
        tile[ty + j][tx] = qkv[(size_t)(rbase + ty + j) * (3 * DIM) + 2 * DIM + cbase + tx];
    __syncthreads();
#pragma unroll
    for (int j = 0; j < 32; j += 8)
        out[(size_t)(cbase + ty + j) * NSEQ + rbase + tx] = tile[tx][ty + j];
}

// ---------------- row softmax: P = softmax(S * 1/32), output tf32-rounded ----------------
__global__ __launch_bounds__(256)
void softmax_kernel(const float* __restrict__ S, float* __restrict__ P) {
    const int row = blockIdx.x;
    const float scale = 0.03125f;   // 1/sqrt(1024)
    const float* s = S + (size_t)row * NSEQ;
    float* p = P + (size_t)row * NSEQ;
    const int tid = threadIdx.x;
    const int lane = tid & 31, warp = tid >> 5;
    __shared__ float sh[8];

    float v[16];
    float mx = -1e30f;
#pragma unroll
    for (int t = 0; t < 16; t++) {
        v[t] = s[tid + t * 256] * scale;
        mx = fmaxf(mx, v[t]);
    }
#pragma unroll
    for (int o = 16; o; o >>= 1) mx = fmaxf(mx, __shfl_xor_sync(0xffffffffu, mx, o));
    if (lane == 0) sh[warp] = mx;
    __syncthreads();
    if (tid == 0) {
        float t = sh[0];
#pragma unroll
        for (int i = 1; i < 8; i++) t = fmaxf(t, sh[i]);
        sh[0] = t;
    }
    __syncthreads();
    mx = sh[0];
    __syncthreads();

    float sum = 0.f;
#pragma unroll
    for (int t = 0; t < 16; t++) {
        v[t] = __expf(v[t] - mx);
        sum += v[t];
    }
#pragma unroll
    for (int o = 16; o; o >>= 1) sum += __shfl_xor_sync(0xffffffffu, sum, o);
    if (lane == 0) sh[warp] = sum;
    __syncthreads();
    if (tid == 0) {
        float t = 0.f;
#pragma unroll
        for (int i = 0; i < 8; i++) t += sh[i];
        sh[0] = t;
    }
    __syncthreads();
    const float inv = 1.0f / sh[0];
#pragma unroll
    for (int t = 0; t < 16; t++) p[tid + t * 256] = to_tf32(v[t] * inv);
}

// ---------------- launch ----------------
extern "C" void kernel_launch(void* const* d_in, const int* in_sizes, int n_in,
                              void* d_out, int out_size) {
    const float* x  = (const float*)d_in[0];
    const float* wq = (const float*)d_in[1];
    const float* wk = (const float*)d_in[2];
    const float* wv = (const float*)d_in[3];
    float* out = (float*)d_out;

    float *p_xt, *p_wt, *p_qkv, *p_vt, *p_S, *p_P;
    cudaGetSymbolAddress((void**)&p_xt, g_xt);
    cudaGetSymbolAddress((void**)&p_wt, g_wt);
    cudaGetSymbolAddress((void**)&p_qkv, g_qkv);
    cudaGetSymbolAddress((void**)&p_vt, g_vt);
    cudaGetSymbolAddress((void**)&p_S, g_S);
    cudaGetSymbolAddress((void**)&p_P, g_P);

    cudaFuncSetAttribute(gemm_tt, cudaFuncAttributeMaxDynamicSharedMemorySize, DYN_SMEM_BYTES);

    // 1) round inputs to tf32
    convert_kernel<<<2048, 256>>>(x, wq, wk, wv);

    // 2) QKV = x @ W^T, W stacked [3072,1024]; output packed [4096, 3072]
    gemm_tt<<<dim3(3 * DIM / BN, NSEQ / BM), 256, DYN_SMEM_BYTES>>>(
        p_xt, DIM, p_wt, DIM, p_qkv, 3 * DIM, NSEQ, 3 * DIM, DIM, 1);

    // 3) V^T for the P@V GEMM
    transpose_v_kernel<<<dim3(DIM / 32, NSEQ / 32), dim3(32, 8)>>>(p_qkv, p_vt);

    // 4) S = Q @ K^T  (M=N=4096, K=1024); Q,K are column slices of packed qkv
    gemm_tt<<<dim3(NSEQ / BN, NSEQ / BM), 256, DYN_SMEM_BYTES>>>(
        p_qkv, 3 * DIM, p_qkv + DIM, 3 * DIM, p_S, NSEQ, NSEQ, NSEQ, DIM, 0);

    // 5) P = softmax(S / 32), tf32-rounded
    softmax_kernel<<<NSEQ, 256>>>(p_S, p_P);

    // 6) out = P @ V = P @ (V^T)^T  (M=4096, N=1024, K=4096)
    gemm_tt<<<dim3(DIM / BN, NSEQ / BM), 256, DYN_SMEM_BYTES>>>(
        p_P, NSEQ, p_vt, NSEQ, out, DIM, NSEQ, DIM, NSEQ, 0);
}